// round 9
// baseline (speedup 1.0000x reference)
#include <cuda_runtime.h>

// PlanarQuantMSE — software-pipelined multi-row kernel.
// 592 CTAs (4/SM x 148), each strides over rows (bid, bid+592, ...), double-
// buffering row data in registers: next row's loads are issued before the
// current row's transform, keeping the DRAM read stream continuous.
// LUT (row-invariant) built once per CTA. One barrier per row (red[2][8]).
// Quantizer = R3's verified byte-LUT: lut[cell] -> L, compare r > mid_sh[L],
// q = c_sh[idx]; broadcast-friendly, exact boundary (rel_err 5.6e-8 class).
// Output: [x_hat | indices-as-float] concatenated.

#define ROWS 4096
#define DIM  4096
#define TPB  256
#define VPT  4        // float4s per thread (TPB*4*VPT == DIM)
#define GRID 592      // 4 CTAs/SM * 148 SMs
#define NCELL 1024
#define SCALEF 455.0f
// magic = 2^23*1.5 + 512 ; cell = bits(fma(v,S,magic)) - 0x4B400000 = round(v*S)+512
// |r| <= 1+3e-7 => cell in [57, 968]: no clamp needed.
#define MAGICF 12583424.0f
#define BITBASE 0x4B400000

__global__ __launch_bounds__(TPB, 4)
void pq_kernel(const float* __restrict__ x,
               const float* __restrict__ cent,
               const float* __restrict__ rot2,
               float* __restrict__ xhat,
               float* __restrict__ idxout)
{
    __shared__ unsigned char lut_sh[NCELL];
    __shared__ float  mid_sh[16];
    __shared__ float  c_sh[16];
    __shared__ int    tc_sh[15];
    __shared__ float  red[2][TPB / 32];
    __shared__ int    flag_sh;

    const int bid = blockIdx.x;
    const int t   = threadIdx.x;
    const int w   = t >> 5;

    // ---- warp-0 setup: centroids, midpoints, cell ids, dup flag ----
    if (t < 16) {
        float cv = __ldg(&cent[t]);
        c_sh[t] = cv;
        float cn = __shfl_down_sync(0x0000ffffu, cv, 1);
        float mm = 0.5f * (cv + cn);
        int cell = __float_as_int(fmaf(mm, SCALEF, MAGICF)) - BITBASE;
        if (t < 15) { mid_sh[t] = mm; tc_sh[t] = cell; }
        else        { mid_sh[15] = 3.0e38f; }
        int celln = __shfl_down_sync(0x0000ffffu, cell, 1);
        unsigned dup = __ballot_sync(0x0000ffffu, (t < 14) && (cell == celln));
        if (t == 0) flag_sh = (dup != 0u) ? 1 : 0;
    }

    // ---- load first row, reduce its sum of squares into red[0] ----
    int row = bid;
    float4 vc[VPT];
    {
        const float4* xr = (const float4*)(x + (size_t)row * DIM);
#pragma unroll
        for (int k = 0; k < VPT; k++) vc[k] = __ldcs(&xr[t + k * TPB]);
        float ss = 0.0f;
#pragma unroll
        for (int k = 0; k < VPT; k++)
            ss += vc[k].x * vc[k].x + vc[k].y * vc[k].y
                + vc[k].z * vc[k].z + vc[k].w * vc[k].w;
#pragma unroll
        for (int o = 16; o > 0; o >>= 1)
            ss += __shfl_xor_sync(0xffffffffu, ss, o);
        if ((t & 31) == 0) red[0][w] = ss;
    }
    __syncthreads();                         // tc_sh + red[0] visible

    // ---- byte-LUT build: 4 cells/thread, one packed STS.32 ----
    {
        const int base = t * 4;
        int L0 = 0, L1 = 0, L2 = 0, L3 = 0;
#pragma unroll
        for (int j = 0; j < 15; j++) {
            int cj = tc_sh[j];
            L0 += (cj < base)     ? 1 : 0;
            L1 += (cj < base + 1) ? 1 : 0;
            L2 += (cj < base + 2) ? 1 : 0;
            L3 += (cj < base + 3) ? 1 : 0;
        }
        ((unsigned int*)lut_sh)[t] =
            (unsigned)L0 | ((unsigned)L1 << 8) | ((unsigned)L2 << 16) | ((unsigned)L3 << 24);
    }
    __syncthreads();                         // lut_sh visible
    const int flag = flag_sh;

    const float4* rr = (const float4*)rot2;  // (c,s,c,s) per float4

    // ---- pipelined row loop ----
    int par = 0;
    while (row < ROWS) {
        const int next = row + GRID;
        const bool has_next = (next < ROWS);

        // issue next row's loads early (overlap with transform below)
        float4 vn[VPT];
        if (has_next) {
            const float4* xn = (const float4*)(x + (size_t)next * DIM);
#pragma unroll
            for (int k = 0; k < VPT; k++) vn[k] = __ldcs(&xn[t + k * TPB]);
        }

        // per-thread norm from the 8 partials (broadcast LDS, no 2nd barrier)
        float s2 = 0.0f;
#pragma unroll
        for (int p = 0; p < TPB / 32; p++) s2 += red[par][p];
        const float norm = fmaxf(sqrtf(s2), 1e-8f);
        const float inv  = 1.0f / norm;

        float4* xo = (float4*)(xhat   + (size_t)row * DIM);
        float4* io = (float4*)(idxout + (size_t)row * DIM);

#pragma unroll
        for (int k = 0; k < VPT; k++) {
            const int j = t + k * TPB;
            const float4 rs = __ldg(&rr[j]);

            const float v0 = vc[k].x * inv, v1 = vc[k].y * inv;
            const float v2 = vc[k].z * inv, v3 = vc[k].w * inv;

            float r[4];
            r[0] = rs.x * v0 - rs.y * v1;
            r[1] = rs.y * v0 + rs.x * v1;
            r[2] = rs.z * v2 - rs.w * v3;
            r[3] = rs.w * v2 + rs.z * v3;

            float q[4], f[4];
            if (!flag) {
#pragma unroll
                for (int e = 0; e < 4; e++) {
                    int cell = __float_as_int(fmaf(r[e], SCALEF, MAGICF)) - BITBASE;
                    int L    = (int)lut_sh[cell];                 // narrow byte LDS
                    int idx  = L + ((r[e] > mid_sh[L]) ? 1 : 0);  // bcast + exact cmp
                    q[e] = c_sh[idx];                             // bcast
                    f[e] = (float)idx;
                }
            } else {
#pragma unroll
                for (int e = 0; e < 4; e++) {
                    int idx = 0;
#pragma unroll
                    for (int jj = 0; jj < 15; jj++) idx += (r[e] > mid_sh[jj]) ? 1 : 0;
                    q[e] = c_sh[idx];
                    f[e] = (float)idx;
                }
            }

            float4 out;
            out.x = (rs.x * q[0] + rs.y * q[1]) * norm;
            out.y = (rs.x * q[1] - rs.y * q[0]) * norm;
            out.z = (rs.z * q[2] + rs.w * q[3]) * norm;
            out.w = (rs.z * q[3] - rs.w * q[2]) * norm;
            __stcs(&xo[j], out);

            float4 fo;
            fo.x = f[0]; fo.y = f[1]; fo.z = f[2]; fo.w = f[3];
            __stcs(&io[j], fo);
        }

        // reduce next row's sum of squares into the other buffer
        if (has_next) {
            float ss = 0.0f;
#pragma unroll
            for (int k = 0; k < VPT; k++)
                ss += vn[k].x * vn[k].x + vn[k].y * vn[k].y
                    + vn[k].z * vn[k].z + vn[k].w * vn[k].w;
#pragma unroll
            for (int o = 16; o > 0; o >>= 1)
                ss += __shfl_xor_sync(0xffffffffu, ss, o);
            if ((t & 31) == 0) red[par ^ 1][w] = ss;
        }
        __syncthreads();                     // red[par^1] visible; red[par] free

        if (has_next) {
#pragma unroll
            for (int k = 0; k < VPT; k++) vc[k] = vn[k];
        }
        row = next;
        par ^= 1;
    }
}

extern "C" void kernel_launch(void* const* d_in, const int* in_sizes, int n_in,
                              void* d_out, int out_size) {
    const float* x = nullptr;
    const float* cent = nullptr;
    const float* rot2 = nullptr;
    for (int i = 0; i < n_in; i++) {
        if (in_sizes[i] == ROWS * DIM) x    = (const float*)d_in[i];
        else if (in_sizes[i] == 16)    cent = (const float*)d_in[i];
        else if (in_sizes[i] == 4096)  rot2 = (const float*)d_in[i];
    }

    float* xhat = (float*)d_out;
    float* idxf = xhat + (long long)ROWS * DIM;

    pq_kernel<<<GRID, TPB>>>(x, cent, rot2, xhat, idxf);
}

// round 10
// speedup vs baseline: 1.0658x; 1.0658x over previous
#include <cuda_runtime.h>

// PlanarQuantMSE — best-of-all-rounds recombination.
// Per-row CTA (R3 structure, 34.3us best kernel), byte-LUT quantizer with
// EXACT verified boundary (lut[cell] -> L; r > mid_sh[L]; q = c_sh[idx]),
// __launch_bounds__(256,6) for occ ~66% (R5/R8: fits 40 regs), no clamp,
// index via I2F (no 3rd LDS), DEFAULT loads/stores (L2 absorbs write stream;
// __stcs measurably hurt in R5/R8 vs R3).
// Output: [x_hat | indices-as-float] concatenated.

#define ROWS 4096
#define DIM  4096
#define TPB  256
#define VPT  4        // float4s per thread (TPB*4*VPT == DIM)
#define NCELL 1024
#define SCALEF 455.0f
// magic = 2^23*1.5 + 512 ; cell = bits(fma(v,S,magic)) - 0x4B400000 = round(v*S)+512
// |r| <= 1+3e-7 (rotated unit-subvector pair) => cell in [57, 968]: no clamp.
#define MAGICF 12583424.0f
#define BITBASE 0x4B400000

__global__ __launch_bounds__(TPB, 6)
void pq_kernel(const float* __restrict__ x,
               const float* __restrict__ cent,
               const float* __restrict__ rot2,
               float* __restrict__ xhat,
               float* __restrict__ idxout)
{
    __shared__ unsigned char lut_sh[NCELL];
    __shared__ float  mid_sh[16];
    __shared__ float  c_sh[16];
    __shared__ int    tc_sh[15];
    __shared__ float  red[TPB / 32];
    __shared__ float  norm_sh;
    __shared__ int    flag_sh;

    const int row = blockIdx.x;
    const int t   = threadIdx.x;

    // ---- issue x loads first so DRAM streams while we do table setup ----
    const float4* xr = (const float4*)(x + (size_t)row * DIM);
    float4 v[VPT];
#pragma unroll
    for (int k = 0; k < VPT; k++) v[k] = xr[t + k * TPB];

    // ---- warp-0 setup: centroids, midpoints, cell ids, dup flag ----
    if (t < 16) {
        float cv = __ldg(&cent[t]);
        c_sh[t] = cv;
        float cn = __shfl_down_sync(0x0000ffffu, cv, 1);
        float mm = 0.5f * (cv + cn);
        int cell = __float_as_int(fmaf(mm, SCALEF, MAGICF)) - BITBASE;
        if (t < 15) { mid_sh[t] = mm; tc_sh[t] = cell; }
        else        { mid_sh[15] = 3.0e38f; }
        int celln = __shfl_down_sync(0x0000ffffu, cell, 1);
        unsigned dup = __ballot_sync(0x0000ffffu, (t < 14) && (cell == celln));
        if (t == 0) flag_sh = (dup != 0u) ? 1 : 0;
    }

    // ---- row sum of squares ----
    float ss = 0.0f;
#pragma unroll
    for (int k = 0; k < VPT; k++)
        ss += v[k].x * v[k].x + v[k].y * v[k].y
            + v[k].z * v[k].z + v[k].w * v[k].w;
#pragma unroll
    for (int o = 16; o > 0; o >>= 1)
        ss += __shfl_xor_sync(0xffffffffu, ss, o);
    if ((t & 31) == 0) red[t >> 5] = ss;
    __syncthreads();                                   // barrier A

    // ---- byte-LUT build: 4 cells/thread, one packed STS.32 ----
    {
        const int base = t * 4;
        int L0 = 0, L1 = 0, L2 = 0, L3 = 0;
#pragma unroll
        for (int j = 0; j < 15; j++) {
            int cj = tc_sh[j];
            L0 += (cj < base)     ? 1 : 0;
            L1 += (cj < base + 1) ? 1 : 0;
            L2 += (cj < base + 2) ? 1 : 0;
            L3 += (cj < base + 3) ? 1 : 0;
        }
        ((unsigned int*)lut_sh)[t] =
            (unsigned)L0 | ((unsigned)L1 << 8) | ((unsigned)L2 << 16) | ((unsigned)L3 << 24);
    }

    if (t < (TPB / 32)) {
        float s2 = red[t];
#pragma unroll
        for (int o = (TPB / 64); o > 0; o >>= 1)
            s2 += __shfl_xor_sync((1u << (TPB / 32)) - 1u, s2, o);
        if (t == 0) norm_sh = fmaxf(sqrtf(s2), 1e-8f);
    }
    __syncthreads();                                   // barrier B

    const float norm = norm_sh;
    const float inv  = 1.0f / norm;
    const int   flag = flag_sh;

    const float4* rr = (const float4*)rot2;            // (c,s,c,s) per float4
    float4* xo = (float4*)(xhat  + (size_t)row * DIM);
    float4* io = (float4*)(idxout + (size_t)row * DIM);

#pragma unroll
    for (int k = 0; k < VPT; k++) {
        const int j = t + k * TPB;
        const float4 rs = __ldg(&rr[j]);

        const float v0 = v[k].x * inv, v1 = v[k].y * inv;
        const float v2 = v[k].z * inv, v3 = v[k].w * inv;

        float r[4];
        r[0] = rs.x * v0 - rs.y * v1;
        r[1] = rs.y * v0 + rs.x * v1;
        r[2] = rs.z * v2 - rs.w * v3;
        r[3] = rs.w * v2 + rs.z * v3;

        float q[4], f[4];
        if (!flag) {
#pragma unroll
            for (int e = 0; e < 4; e++) {
                int cell = __float_as_int(fmaf(r[e], SCALEF, MAGICF)) - BITBASE;
                int L    = (int)lut_sh[cell];                 // narrow byte LDS
                int idx  = L + ((r[e] > mid_sh[L]) ? 1 : 0);  // bcast + exact cmp
                q[e] = c_sh[idx];                             // bcast
                f[e] = (float)idx;
            }
        } else {
#pragma unroll
            for (int e = 0; e < 4; e++) {
                int idx = 0;
#pragma unroll
                for (int jj = 0; jj < 15; jj++) idx += (r[e] > mid_sh[jj]) ? 1 : 0;
                q[e] = c_sh[idx];
                f[e] = (float)idx;
            }
        }

        float4 out;
        out.x = (rs.x * q[0] + rs.y * q[1]) * norm;
        out.y = (rs.x * q[1] - rs.y * q[0]) * norm;
        out.z = (rs.z * q[2] + rs.w * q[3]) * norm;
        out.w = (rs.z * q[3] - rs.w * q[2]) * norm;
        xo[j] = out;                                   // DEFAULT store: L2 absorbs

        float4 fo;
        fo.x = f[0]; fo.y = f[1]; fo.z = f[2]; fo.w = f[3];
        io[j] = fo;
    }
}

extern "C" void kernel_launch(void* const* d_in, const int* in_sizes, int n_in,
                              void* d_out, int out_size) {
    const float* x = nullptr;
    const float* cent = nullptr;
    const float* rot2 = nullptr;
    for (int i = 0; i < n_in; i++) {
        if (in_sizes[i] == ROWS * DIM) x    = (const float*)d_in[i];
        else if (in_sizes[i] == 16)    cent = (const float*)d_in[i];
        else if (in_sizes[i] == 4096)  rot2 = (const float*)d_in[i];
    }

    float* xhat = (float*)d_out;
    float* idxf = xhat + (long long)ROWS * DIM;

    pq_kernel<<<ROWS, TPB>>>(x, cent, rot2, xhat, idxf);
}